// round 14
// baseline (speedup 1.0000x reference)
#include <cuda_runtime.h>
#include <cuda_bf16.h>

// Problem constants (fixed by the reference setup)
#define BZ 64
#define P  512
#define T  256
#define H  768
#define H4 (H / 4)       // 192 float4 per row
#define BLK_PER_B 32     // sub-blocks per batch
#define TOK_PER_BLK (T / BLK_PER_B)  // 8 tokens per block = 8 warps

// 256-bit global load (sm_103a LDG.256): one instruction fetches 32B/lane.
__device__ __forceinline__ void ld256(const float4* p, float4& a, float4& b) {
    unsigned r0, r1, r2, r3, r4, r5, r6, r7;
    asm("ld.global.v8.b32 {%0,%1,%2,%3,%4,%5,%6,%7}, [%8];"
        : "=r"(r0), "=r"(r1), "=r"(r2), "=r"(r3),
          "=r"(r4), "=r"(r5), "=r"(r6), "=r"(r7)
        : "l"(p));
    a = make_float4(__uint_as_float(r0), __uint_as_float(r1),
                    __uint_as_float(r2), __uint_as_float(r3));
    b = make_float4(__uint_as_float(r4), __uint_as_float(r5),
                    __uint_as_float(r6), __uint_as_float(r7));
}

// Fused kernel (R6 structure + 256-bit loads): block scans its batch's lens,
// then pools 8 tokens, one warp per token. Each lane covers 2 adjacent
// float4s per 1KB chunk, 3 chunks per 3072B row.
__global__ __launch_bounds__(256, 6) void fused_pool_kernel(
    const float4* __restrict__ enc,   // (BZ, P, H4)
    const int* __restrict__ lens,     // (BZ, T)
    float4* __restrict__ out)         // (BZ, T, H4)
{
    const int warp = threadIdx.x >> 5;
    const int lane = threadIdx.x & 31;
    const int b    = blockIdx.x / BLK_PER_B;
    const int tok0 = (blockIdx.x % BLK_PER_B) * TOK_PER_BLK;

    // ---- block-wide exclusive scan of lens[b, 0..255] -> packed desc ----
    __shared__ int s_warpsum[8];
    __shared__ int s_desc[T];         // start | len<<16 per token

    const int t = threadIdx.x;        // 0..255 == token index
    int v = __ldg(&lens[b * T + t]);

    int x = v;
    #pragma unroll
    for (int off = 1; off < 32; off <<= 1) {
        int y = __shfl_up_sync(0xffffffffu, x, off);
        if (lane >= off) x += y;
    }
    if (lane == 31) s_warpsum[warp] = x;
    __syncthreads();
    if (warp == 0 && lane < 8) {
        int w = s_warpsum[lane];
        #pragma unroll
        for (int off = 1; off < 8; off <<= 1) {
            int y = __shfl_up_sync(0xffu, w, off);
            if (lane >= off) w += y;
        }
        s_warpsum[lane] = w - s_warpsum[lane];   // exclusive warp offsets
    }
    __syncthreads();
    const int start_t = x - v + s_warpsum[warp]; // exclusive prefix for token t
    s_desc[t] = start_t | (v << 16);
    __syncthreads();

    // ---- pooling: warp handles token tok0 + warp ----
    const int tok   = tok0 + warp;
    const int desc  = s_desc[tok];
    const int start = desc & 0xffff;
    const int len   = desc >> 16;

    // lane covers float4 indices 64*c + lane*2 and +1 for chunk c in {0,1,2}
    float4* obase = out + ((size_t)b * T + tok) * H4 + lane * 2;

    if (len == 0) {
        const float4 z = make_float4(0.f, 0.f, 0.f, 0.f);
        #pragma unroll
        for (int c = 0; c < 3; ++c) {
            __stcs(obase + 64 * c,     z);
            __stcs(obase + 64 * c + 1, z);
        }
        return;
    }

    const float4* row = enc + ((size_t)b * P + start) * H4 + lane * 2;

    if (len == 1) {
        #pragma unroll
        for (int c = 0; c < 3; ++c) {
            float4 a, bb;
            ld256(row + 64 * c, a, bb);
            __stcs(obase + 64 * c,     a);
            __stcs(obase + 64 * c + 1, bb);
        }
    } else if (len == 2) {
        #pragma unroll
        for (int c = 0; c < 3; ++c) {
            float4 a0, a1, b0, b1;
            ld256(row + 64 * c,      a0, a1);
            ld256(row + H4 + 64 * c, b0, b1);
            a0.x = (a0.x + b0.x) * 0.5f; a0.y = (a0.y + b0.y) * 0.5f;
            a0.z = (a0.z + b0.z) * 0.5f; a0.w = (a0.w + b0.w) * 0.5f;
            a1.x = (a1.x + b1.x) * 0.5f; a1.y = (a1.y + b1.y) * 0.5f;
            a1.z = (a1.z + b1.z) * 0.5f; a1.w = (a1.w + b1.w) * 0.5f;
            __stcs(obase + 64 * c,     a0);
            __stcs(obase + 64 * c + 1, a1);
        }
    } else {
        // general fallback (not hit by this dataset, but stay correct)
        const float inv = 1.0f / (float)len;
        #pragma unroll
        for (int c = 0; c < 3; ++c) {
            float4 acc0, acc1;
            ld256(row + 64 * c, acc0, acc1);
            for (int j = 1; j < len; ++j) {
                float4 r0, r1;
                ld256(row + (size_t)j * H4 + 64 * c, r0, r1);
                acc0.x += r0.x; acc0.y += r0.y; acc0.z += r0.z; acc0.w += r0.w;
                acc1.x += r1.x; acc1.y += r1.y; acc1.z += r1.z; acc1.w += r1.w;
            }
            acc0.x *= inv; acc0.y *= inv; acc0.z *= inv; acc0.w *= inv;
            acc1.x *= inv; acc1.y *= inv; acc1.z *= inv; acc1.w *= inv;
            __stcs(obase + 64 * c,     acc0);
            __stcs(obase + 64 * c + 1, acc1);
        }
    }
}

extern "C" void kernel_launch(void* const* d_in, const int* in_sizes, int n_in,
                              void* d_out, int out_size) {
    const float* enc_out   = (const float*)d_in[0];   // (BZ, P, H) f32
    // d_in[1] = bert_mask (unused; lens fully determine the mapping)
    const int*   bert_lens = (const int*)d_in[2];     // (BZ, T) i32
    float* out = (float*)d_out;                       // (BZ, T, H) f32

    fused_pool_kernel<<<BZ * BLK_PER_B, 256>>>(
        (const float4*)enc_out, bert_lens, (float4*)out);
}

// round 15
// speedup vs baseline: 1.4419x; 1.4419x over previous
#include <cuda_runtime.h>
#include <cuda_bf16.h>

// Problem constants (fixed by the reference setup)
#define BZ 64
#define P  512
#define T  256
#define H  768
#define H4 (H / 4)       // 192 float4 per row
#define BLK_PER_B 32     // sub-blocks per batch
#define TOK_PER_BLK (T / BLK_PER_B)  // 8 tokens per block = 8 warps

// FINAL (best measured config, R6):
//  - fused lens-scan + pool, one warp per token, 2 halves x 3 float4 per lane
//  - default-cached LDG.128 loads (beat evict-last 1.0/0.5, cache_hint, LDG.256)
//  - __stcs evict-first stores for the write-once output stream (beat __stwt)
//  - __launch_bounds__(256, 6): 6 blocks/SM optimum (3 and 8 both slower)
// Moves ~117MB at 14.9-17us wall => ~7-8TB/s: at the HBM roofline.
__global__ __launch_bounds__(256, 6) void fused_pool_kernel(
    const float4* __restrict__ enc,   // (BZ, P, H4)
    const int* __restrict__ lens,     // (BZ, T)
    float4* __restrict__ out)         // (BZ, T, H4)
{
    const int warp = threadIdx.x >> 5;
    const int lane = threadIdx.x & 31;
    const int b    = blockIdx.x / BLK_PER_B;
    const int tok0 = (blockIdx.x % BLK_PER_B) * TOK_PER_BLK;

    // ---- block-wide exclusive scan of lens[b, 0..255] -> packed desc ----
    __shared__ int s_warpsum[8];
    __shared__ int s_desc[T];         // start | len<<16 per token

    const int t = threadIdx.x;        // 0..255 == token index
    int v = __ldg(&lens[b * T + t]);

    int x = v;
    #pragma unroll
    for (int off = 1; off < 32; off <<= 1) {
        int y = __shfl_up_sync(0xffffffffu, x, off);
        if (lane >= off) x += y;
    }
    if (lane == 31) s_warpsum[warp] = x;
    __syncthreads();
    if (warp == 0 && lane < 8) {
        int w = s_warpsum[lane];
        #pragma unroll
        for (int off = 1; off < 8; off <<= 1) {
            int y = __shfl_up_sync(0xffu, w, off);
            if (lane >= off) w += y;
        }
        s_warpsum[lane] = w - s_warpsum[lane];   // exclusive warp offsets
    }
    __syncthreads();
    const int start_t = x - v + s_warpsum[warp]; // exclusive prefix for token t
    s_desc[t] = start_t | (v << 16);
    __syncthreads();

    // ---- pooling: warp handles token tok0 + warp ----
    const int tok   = tok0 + warp;
    const int desc  = s_desc[tok];
    const int start = desc & 0xffff;
    const int len   = desc >> 16;

    float4* obase = out + ((size_t)b * T + tok) * H4 + lane;

    if (len == 0) {
        const float4 z = make_float4(0.f, 0.f, 0.f, 0.f);
        #pragma unroll
        for (int i = 0; i < 6; ++i) __stcs(obase + 32 * i, z);
        return;
    }

    const float4* row = enc + ((size_t)b * P + start) * H4 + lane;

    if (len == 1) {
        #pragma unroll
        for (int half = 0; half < 2; ++half) {
            float4 a0 = row[96 * half + 0];
            float4 a1 = row[96 * half + 32];
            float4 a2 = row[96 * half + 64];
            __stcs(obase + 96 * half + 0,  a0);
            __stcs(obase + 96 * half + 32, a1);
            __stcs(obase + 96 * half + 64, a2);
        }
    } else if (len == 2) {
        #pragma unroll
        for (int half = 0; half < 2; ++half) {
            float4 a0 = row[96 * half + 0];
            float4 a1 = row[96 * half + 32];
            float4 a2 = row[96 * half + 64];
            float4 b0 = row[H4 + 96 * half + 0];
            float4 b1 = row[H4 + 96 * half + 32];
            float4 b2 = row[H4 + 96 * half + 64];
            a0.x = (a0.x + b0.x) * 0.5f; a0.y = (a0.y + b0.y) * 0.5f;
            a0.z = (a0.z + b0.z) * 0.5f; a0.w = (a0.w + b0.w) * 0.5f;
            a1.x = (a1.x + b1.x) * 0.5f; a1.y = (a1.y + b1.y) * 0.5f;
            a1.z = (a1.z + b1.z) * 0.5f; a1.w = (a1.w + b1.w) * 0.5f;
            a2.x = (a2.x + b2.x) * 0.5f; a2.y = (a2.y + b2.y) * 0.5f;
            a2.z = (a2.z + b2.z) * 0.5f; a2.w = (a2.w + b2.w) * 0.5f;
            __stcs(obase + 96 * half + 0,  a0);
            __stcs(obase + 96 * half + 32, a1);
            __stcs(obase + 96 * half + 64, a2);
        }
    } else {
        // general fallback (not hit by this dataset, but stay correct)
        const float inv = 1.0f / (float)len;
        #pragma unroll
        for (int half = 0; half < 2; ++half) {
            #pragma unroll
            for (int i = 0; i < 3; ++i) {
                const int off = 96 * half + 32 * i;
                float4 acc = row[off];
                for (int j = 1; j < len; ++j) {
                    float4 r2 = row[(size_t)j * H4 + off];
                    acc.x += r2.x; acc.y += r2.y; acc.z += r2.z; acc.w += r2.w;
                }
                acc.x *= inv; acc.y *= inv; acc.z *= inv; acc.w *= inv;
                __stcs(obase + off, acc);
            }
        }
    }
}

extern "C" void kernel_launch(void* const* d_in, const int* in_sizes, int n_in,
                              void* d_out, int out_size) {
    const float* enc_out   = (const float*)d_in[0];   // (BZ, P, H) f32
    // d_in[1] = bert_mask (unused; lens fully determine the mapping)
    const int*   bert_lens = (const int*)d_in[2];     // (BZ, T) i32
    float* out = (float*)d_out;                       // (BZ, T, H) f32

    fused_pool_kernel<<<BZ * BLK_PER_B, 256>>>(
        (const float4*)enc_out, bert_lens, (float4*)out);
}